// round 17
// baseline (speedup 1.0000x reference)
#include <cuda_runtime.h>

// L1Distance, FFMA-imm (rt1) math + high-duty geometry:
//   t   = fmaf(a, 2.0f, -b2)        (b2 = 2b staged)   FFMA R,R,2.0,-R   rt1
//   acc = fmaf(|t|, 2.0f, acc)                         FFMA R,|R|,2.0,R  rt1
//   out = max(0.25f * acc, 0)       (exact /4; mean-adjustment cancels)
// 64x128 tile, 4x8 per thread (32 accs, ~64 regs) -> 4 CTAs/SM = 8 warps/SMSP
// for issue-duty; 512-CTA grid = single wave. Math slots unchanged (28.3K/SMSP),
// register-pressure overhead and latency exposure reduced.

constexpr int D   = 64;
constexpr int TM  = 64;    // tile rows (x1)
constexpr int TN  = 128;   // tile cols (x2)
constexpr int DC  = 32;    // d staged in two chunks
constexpr int STA = 68;    // As stride (64 + 4 pad)
constexpr int STB = 132;   // Bs stride (128 + 4 pad)

__global__ __launch_bounds__(256, 4)
void l1dist_kernel(const float* __restrict__ x1, const float* __restrict__ x2,
                   float* __restrict__ out, int N2) {
    __shared__ __align__(16) float As[DC * STA];  // As[d][row] = x1[i0+row][dc+d]
    __shared__ __align__(16) float Bs[DC * STB];  // Bs[d][row] = 2*x2[j0+row][dc+d]

    const int i0  = blockIdx.y * TM;
    const int j0  = blockIdx.x * TN;
    const int tid = (int)threadIdx.x;
    const int ty  = tid >> 4;   // 0..15 -> rows ty*4 .. ty*4+3
    const int tx  = tid & 15;   // 0..15 -> cols tx*4+{0..3}, 64+tx*4+{0..3}

    float acc[4][8];
#pragma unroll
    for (int m = 0; m < 4; m++)
#pragma unroll
        for (int n = 0; n < 8; n++) acc[m][n] = 0.0f;

    for (int dc = 0; dc < D; dc += DC) {
        // ---- stage A: 64 rows x 32 d = 512 float4, 2 per thread ----
#pragma unroll
        for (int k = 0; k < 2; k++) {
            int idx = tid + k * 256;        // 0..511
            int row = idx >> 3;             // 0..63
            int d4  = (idx & 7) << 2;       // 0,4,...,28
            float4 a = *(const float4*)(x1 + (size_t)(i0 + row) * D + dc + d4);
            As[(d4 + 0) * STA + row] = a.x;
            As[(d4 + 1) * STA + row] = a.y;
            As[(d4 + 2) * STA + row] = a.z;
            As[(d4 + 3) * STA + row] = a.w;
        }
        // ---- stage B (scaled x2): 128 rows x 32 d = 1024 float4, 4/thread ----
#pragma unroll
        for (int k = 0; k < 4; k++) {
            int idx = tid + k * 256;        // 0..1023
            int row = idx >> 3;             // 0..127
            int d4  = (idx & 7) << 2;
            float4 b = *(const float4*)(x2 + (size_t)(j0 + row) * D + dc + d4);
            Bs[(d4 + 0) * STB + row] = 2.0f * b.x;
            Bs[(d4 + 1) * STB + row] = 2.0f * b.y;
            Bs[(d4 + 2) * STB + row] = 2.0f * b.z;
            Bs[(d4 + 3) * STB + row] = 2.0f * b.w;
        }
        __syncthreads();

        // ---- compute: per d, 3 LDS.128 + 64 FFMA-imm (rt1) ----
#pragma unroll 4
        for (int d = 0; d < DC; d++) {
            float4 av = *(const float4*)(&As[d * STA] + ty * 4);
            float4 b0 = *(const float4*)(&Bs[d * STB] + tx * 4);
            float4 b1 = *(const float4*)(&Bs[d * STB] + tx * 4 + 64);
            float ra[4] = {av.x, av.y, av.z, av.w};
            float rb[8] = {b0.x, b0.y, b0.z, b0.w, b1.x, b1.y, b1.z, b1.w};
#pragma unroll
            for (int m = 0; m < 4; m++)
#pragma unroll
                for (int n = 0; n < 8; n++) {
                    float t = fmaf(ra[m], 2.0f, -rb[n]);          // 2a - 2b
                    acc[m][n] = fmaf(fabsf(t), 2.0f, acc[m][n]);  // += 4|a-b|
                }
        }
        __syncthreads();
    }

    // ---- store: out = max(acc/4, 0) ----
#pragma unroll
    for (int m = 0; m < 4; m++) {
        int r = i0 + ty * 4 + m;
        float* orow = out + (size_t)r * N2 + j0 + tx * 4;
#pragma unroll
        for (int n4 = 0; n4 < 2; n4++) {
            float4 v = make_float4(
                fmaxf(0.25f * acc[m][n4 * 4 + 0], 0.f),
                fmaxf(0.25f * acc[m][n4 * 4 + 1], 0.f),
                fmaxf(0.25f * acc[m][n4 * 4 + 2], 0.f),
                fmaxf(0.25f * acc[m][n4 * 4 + 3], 0.f));
            *(float4*)(orow + (n4 << 6)) = v;
        }
    }
}

extern "C" void kernel_launch(void* const* d_in, const int* in_sizes, int n_in,
                              void* d_out, int out_size) {
    const float* x1 = (const float*)d_in[0];
    const float* x2 = (const float*)d_in[1];
    float* out = (float*)d_out;

    int N1 = in_sizes[0] / D;   // 2048
    int N2 = in_sizes[1] / D;   // 2048

    dim3 grid(N2 / TN, N1 / TM);   // 16 x 32 = 512 blocks (single wave @ 4/SM)
    l1dist_kernel<<<grid, 256>>>(x1, x2, out, N2);
}